// round 8
// baseline (speedup 1.0000x reference)
#include <cuda_runtime.h>
#include <cfloat>

#define T_DIM 2048
#define R_DIM 256
#define BS_DIM 32
#define IDX(t) ((t) + ((t) >> 5))   // smem skew: 1 pad float per 32
#define CSK 2112                    // skewed column size: 2048 + 64

#define N_MIN_ITEMS 1024
#define N_CDF_ITEMS 1024
#define N_W2_ITEMS  4096
#define ITEMS_TOTAL (N_MIN_ITEMS + N_CDF_ITEMS + N_W2_ITEMS)

// 128 MB transposed CDF scratch: [array][bs][r][t]
__device__ float g_cdf[2][BS_DIM][R_DIM][T_DIM];
// per-segment totals (segments of 128 t): [array][bs][r][seg16]
__device__ float g_segtot[2][BS_DIM][R_DIM][16];
__device__ unsigned int g_min_bits;
__device__ int g_minctr;                   // completed min items
__device__ int g_done[2][BS_DIM][8];       // per (a,bs,rtile): ++ per t-half, target 2
__device__ int g_ctr;                      // work-item counter

__global__ void init_kernel(float* out) {
    int t = threadIdx.x;
    if (t < 4) out[t] = 0.0f;
    if (t == 4) { g_min_bits = 0xFFFFFFFFu; g_minctr = 0; g_ctr = 0; }
    int* d = &g_done[0][0][0];
    for (int i = t; i < 2 * BS_DIM * 8; i += blockDim.x) d[i] = 0;
}

__device__ __forceinline__ unsigned int float_to_key(float f) {
    unsigned int b = __float_as_uint(f);
    return (b & 0x80000000u) ? ~b : (b | 0x80000000u);
}

__global__ void __launch_bounds__(256) fused_kernel(const float* __restrict__ x,
                                                    const float* __restrict__ y,
                                                    float* __restrict__ out) {
    __shared__ union {
        float tile[8][32][33];       // cdf phase: 33.8 KB
        float sm[4 * CSK + 32];      // w2 phase: 33.9 KB (+32 pad for dead loads)
    } U;
    __shared__ float wmin[8];
    __shared__ float coffs[4][16];
    __shared__ float cinvA[4];
    __shared__ float csinvA[4];
    __shared__ float warr[8];
    __shared__ int s_item;

    const int tid = threadIdx.x;

    for (;;) {
        __syncthreads();                       // smem reuse + s_item protect
        if (tid == 0) s_item = atomicAdd(&g_ctr, 1);
        __syncthreads();
        const int item = s_item;
        if (item >= ITEMS_TOTAL) return;

        if (item < N_MIN_ITEMS) {
            // ================= MIN item: 8192 float4 coalesced =================
            const int m = item;
            const float4* p = (m < 512 ? (const float4*)x : (const float4*)y)
                              + (size_t)(m & 511) * 8192;
            float mn = FLT_MAX;
            #pragma unroll 8
            for (int k = 0; k < 32; k++) {
                float4 v = p[k * 256 + tid];
                mn = fminf(mn, fminf(fminf(v.x, v.y), fminf(v.z, v.w)));
            }
            for (int o = 16; o; o >>= 1) mn = fminf(mn, __shfl_xor_sync(0xffffffffu, mn, o));
            if ((tid & 31) == 0) wmin[tid >> 5] = mn;
            __syncthreads();
            if (tid == 0) {
                float v = wmin[0];
                #pragma unroll
                for (int i = 1; i < 8; i++) v = fminf(v, wmin[i]);
                atomicMin(&g_min_bits, float_to_key(v));
                __threadfence();
                atomicAdd(&g_minctr, 1);
            }
        } else if (item < N_MIN_ITEMS + N_CDF_ITEMS) {
            // ================= CDF item: transpose + segment cumsum =================
            const int c    = item - N_MIN_ITEMS;
            const int a    = c & 1;              // interleaved arrays: both done early per bs
            const int c2   = c >> 1;
            const int bs   = c2 >> 4;
            const int rem2 = c2 & 15;
            const int r0   = (rem2 >> 1) * 32;
            const int tb   = (rem2 & 1) * 1024;
            const int rt   = rem2 >> 1;

            const int lane = tid & 31;
            const int seg  = tid >> 5;
            const float* src = (a ? y : x) + (size_t)bs * T_DIM * R_DIM + r0 + lane;

            float run = 0.0f;
            const int row = lane >> 3;
            const int c4  = lane & 7;

            #pragma unroll 1
            for (int ch = 0; ch < 4; ch++) {
                const int t0 = tb + seg * 128 + ch * 32;
                float v[32];
                #pragma unroll
                for (int i = 0; i < 32; i++) v[i] = src[(size_t)(t0 + i) * R_DIM];
                #pragma unroll
                for (int i = 0; i < 32; i++) {
                    run += v[i];
                    U.tile[seg][lane][i] = run;
                }
                __syncwarp();
                #pragma unroll
                for (int rb = 0; rb < 8; rb++) {
                    int rr = rb * 4 + row;
                    float4 o;
                    o.x = U.tile[seg][rr][c4 * 4 + 0];
                    o.y = U.tile[seg][rr][c4 * 4 + 1];
                    o.z = U.tile[seg][rr][c4 * 4 + 2];
                    o.w = U.tile[seg][rr][c4 * 4 + 3];
                    *(float4*)&g_cdf[a][bs][r0 + rr][t0 + c4 * 4] = o;
                }
                __syncwarp();
            }
            g_segtot[a][bs][r0 + lane][(tb >> 7) + seg] = run;

            __threadfence();                // every thread publishes its own stores
            __syncthreads();
            if (tid == 0) atomicAdd(&g_done[a][bs][rt], 1);
        } else {
            // ================= W2 item: wait -> stage -> merge =================
            const int w  = item - (N_MIN_ITEMS + N_CDF_ITEMS);
            const int bs = w >> 7;
            const int r0 = (w & 127) * 2;
            const int rt = r0 >> 5;

            if (tid == 0) {
                volatile int* mc = &g_minctr;
                while (*mc < N_MIN_ITEMS) __nanosleep(64);
                volatile int* d0 = &g_done[0][bs][rt];
                volatile int* d1 = &g_done[1][bs][rt];
                while (*d0 < 2) __nanosleep(64);
                while (*d1 < 2) __nanosleep(64);
                __threadfence();
            }
            __syncthreads();

            unsigned int k = g_min_bits;
            float mnv = (k & 0x80000000u) ? __uint_as_float(k & 0x7FFFFFFFu)
                                          : __uint_as_float(~k);
            const float shift = (mnv < 0.0f) ? (-1.1f * mnv) : 0.0f;

            if (tid < 4) {
                int c = tid, aa = c & 1, pp = c >> 1;
                const float* st = g_segtot[aa][bs][r0 + pp];
                float pref[16];
                float runp = 0.0f;
                #pragma unroll
                for (int s = 0; s < 16; s++) { pref[s] = runp; runp += st[s]; }
                float inv = 1.0f / (runp + 2048.0f * shift);
                cinvA[c] = inv;
                csinvA[c] = shift * inv;
                #pragma unroll
                for (int s = 0; s < 16; s++) coffs[c][s] = pref[s] * inv;
            }
            __syncthreads();

            {
                const int c = tid >> 6;
                const int l64 = tid & 63;
                const int aa = c & 1, pp = c >> 1;
                const float4* srcc = (const float4*)&g_cdf[aa][bs][r0 + pp][0];
                float* dst = U.sm + c * CSK;
                const float inv = cinvA[c];
                const float si  = csinvA[c];
                const float si2 = si + si;
                float tf = (float)(l64 * 4);
                #pragma unroll
                for (int it = 0; it < 8; it++) {
                    int t4 = it * 64 + l64;
                    float4 v = srcc[t4];
                    int t = t4 * 4;
                    float base = fmaf(tf + 1.0f, si, coffs[c][t >> 7]);
                    dst[IDX(t + 0)] = fmaf(v.x, inv, base);
                    dst[IDX(t + 1)] = fmaf(v.y, inv, base + si);
                    dst[IDX(t + 2)] = fmaf(v.z, inv, base + si2);
                    dst[IDX(t + 3)] = fmaf(v.w, inv, base + si2 + si);
                    tf += 256.0f;
                }
            }
            __syncthreads();

            const int p = tid >> 7;
            const int l = tid & 127;
            const int k0 = l * 32;
            const float* A = U.sm + (p * 2 + 0) * CSK;
            const float* B = U.sm + (p * 2 + 1) * CSK;

            int lo = (k0 > T_DIM) ? (k0 - T_DIM) : 0;
            int hi = (k0 < T_DIM) ? k0 : T_DIM;
            while (lo < hi) {
                int mid = (lo + hi) >> 1;
                if (A[IDX(mid)] <= B[IDX(k0 - 1 - mid)]) lo = mid + 1;
                else hi = mid;
            }
            int i = lo;
            int j = k0 - lo;

            float prevA = i ? A[IDX(i - 1)] : 0.0f;
            float prevB = j ? B[IDX(j - 1)] : 0.0f;
            float prev = fmaxf(prevA, prevB);
            float aq = (i < T_DIM) ? A[IDX(i)] : FLT_MAX;
            float bq = (j < T_DIM) ? B[IDX(j)] : FLT_MAX;

            float acc = 0.0f;
            if ((tid & 64) == 0) {
                float fd = (float)(i - j);
                #pragma unroll 8
                for (int s = 0; s < 32; s++) {
                    bool takeA = (aq <= bq);
                    float q = fminf(aq, bq);
                    acc += (q - prev) * (fd * fd);
                    prev = q;
                    fd += takeA ? 1.0f : -1.0f;
                    if (takeA) { i++; aq = A[IDX(i)]; }
                    else       { j++; bq = B[IDX(j)]; }
                }
            } else {
                #pragma unroll 8
                for (int s = 0; s < 32; s++) {
                    bool takeA = (aq <= bq);
                    float q = fminf(aq, bq);
                    int ic = (i < 2047) ? i : 2047;
                    int jc = (j < 2047) ? j : 2047;
                    float diff = (float)(ic - jc);
                    acc += (q - prev) * (diff * diff);
                    prev = q;
                    if (takeA) { i++; aq = (i < T_DIM) ? A[IDX(i)] : FLT_MAX; }
                    else       { j++; bq = (j < T_DIM) ? B[IDX(j)] : FLT_MAX; }
                }
            }
            acc *= (1.0f / 2048.0f) * (1.0f / 2048.0f);

            for (int o = 16; o; o >>= 1) acc += __shfl_xor_sync(0xffffffffu, acc, o);
            if ((tid & 31) == 0) warr[tid >> 5] = acc;
            __syncthreads();
            if (tid == 0) {
                float s = 0.0f;
                #pragma unroll
                for (int i2 = 0; i2 < 8; i2++) s += warr[i2];
                atomicAdd(&out[bs >> 3], s);
            }
        }
    }
}

extern "C" void kernel_launch(void* const* d_in, const int* in_sizes, int n_in,
                              void* d_out, int out_size) {
    const float* x = (const float*)d_in[0];
    const float* y = (const float*)d_in[1];
    float* out = (float*)d_out;

    init_kernel<<<1, 256>>>(out);
    fused_kernel<<<1024, 256>>>(x, y, out);
}

// round 10
// speedup vs baseline: 1.1471x; 1.1471x over previous
#include <cuda_runtime.h>
#include <cfloat>

#define T_DIM 2048
#define R_DIM 256
#define BS_DIM 32
#define IDX(t) ((t) + ((t) >> 5))   // smem skew: 1 pad float per 32
#define CSK 2112                    // skewed column size: 2048 + 64

// 128 MB transposed CDF scratch: [array][bs][r][t]
__device__ float g_cdf[2][BS_DIM][R_DIM][T_DIM];
// per-segment totals (segments of 128 t): [array][bs][r][seg16]
__device__ float g_segtot[2][BS_DIM][R_DIM][16];
// per-K1-block minima (1024 entries, fully overwritten each call)
__device__ float g_blockmin[1024];

struct SmemU {
    union {
        float tile[8][32][33];       // cdf: 33.8 KB
        float sm[4 * CSK + 32];      // w2: 33.9 KB (+ pad for dead loads)
    };
    float wmin[8];
    float coffs[4][16];
    float cinv[4];
    float csinv[4];
    float warr[8];
};

// ---------------- cdf body: transpose + segment cumsum (one [a][bs][rtile32][thalf]) ----------------
__device__ __forceinline__ float do_cdf(const float* __restrict__ src0, int a, int bs,
                                        int r0, int tb, SmemU* S, int lane, int seg,
                                        bool trackmin) {
    const float* src = src0 + (size_t)bs * T_DIM * R_DIM + r0 + lane;
    float run = 0.0f, mn = FLT_MAX;
    const int row = lane >> 3;
    const int c4  = lane & 7;
    float (*tile)[33] = S->tile[seg];

    #pragma unroll 1
    for (int ch = 0; ch < 4; ch++) {
        const int t0 = tb + seg * 128 + ch * 32;
        #pragma unroll
        for (int h = 0; h < 2; h++) {
            float v[16];
            #pragma unroll
            for (int i = 0; i < 16; i++)
                v[i] = src[(size_t)(t0 + h * 16 + i) * R_DIM];
            #pragma unroll
            for (int i = 0; i < 16; i++) {
                if (trackmin) mn = fminf(mn, v[i]);
                run += v[i];
                tile[lane][h * 16 + i] = run;
            }
        }
        __syncwarp();
        #pragma unroll
        for (int rb = 0; rb < 8; rb++) {
            int rr = rb * 4 + row;
            float4 o;
            o.x = tile[rr][c4 * 4 + 0];
            o.y = tile[rr][c4 * 4 + 1];
            o.z = tile[rr][c4 * 4 + 2];
            o.w = tile[rr][c4 * 4 + 3];
            *(float4*)&g_cdf[a][bs][r0 + rr][t0 + c4 * 4] = o;
        }
        __syncwarp();
    }
    g_segtot[a][bs][r0 + lane][(tb >> 7) + seg] = run;
    return mn;
}

// ---------------- w2 body: stage normalized CDFs + merge-path (one [bs][rpair]) ----------------
__device__ __forceinline__ void do_w2(int bs, int r0, float* __restrict__ out, SmemU* S,
                                      int tid) {
    // global min from g_blockmin (1024 entries, L2-resident)
    {
        float m = fminf(fminf(g_blockmin[tid],       g_blockmin[tid + 256]),
                        fminf(g_blockmin[tid + 512], g_blockmin[tid + 768]));
        for (int o = 16; o; o >>= 1) m = fminf(m, __shfl_xor_sync(0xffffffffu, m, o));
        if ((tid & 31) == 0) S->wmin[tid >> 5] = m;
    }
    __syncthreads();
    float mnv = S->wmin[0];
    #pragma unroll
    for (int i = 1; i < 8; i++) mnv = fminf(mnv, S->wmin[i]);
    const float shift = (mnv < 0.0f) ? (-1.1f * mnv) : 0.0f;

    if (tid < 4) {
        int c = tid, aa = c & 1, pp = c >> 1;
        const float* st = g_segtot[aa][bs][r0 + pp];
        float pref[16];
        float runp = 0.0f;
        #pragma unroll
        for (int s = 0; s < 16; s++) { pref[s] = runp; runp += st[s]; }
        float inv = 1.0f / (runp + 2048.0f * shift);
        S->cinv[c] = inv;
        S->csinv[c] = shift * inv;
        #pragma unroll
        for (int s = 0; s < 16; s++) S->coffs[c][s] = pref[s] * inv;
    }
    __syncthreads();

    {
        const int c = tid >> 6;
        const int l64 = tid & 63;
        const int aa = c & 1, pp = c >> 1;
        const float4* srcc = (const float4*)&g_cdf[aa][bs][r0 + pp][0];
        float* dst = S->sm + c * CSK;
        const float inv = S->cinv[c];
        const float si  = S->csinv[c];
        const float si2 = si + si;
        float tf = (float)(l64 * 4);
        #pragma unroll
        for (int it = 0; it < 8; it++) {
            int t4 = it * 64 + l64;
            float4 v = srcc[t4];
            int t = t4 * 4;
            float base = fmaf(tf + 1.0f, si, S->coffs[c][t >> 7]);
            dst[IDX(t + 0)] = fmaf(v.x, inv, base);
            dst[IDX(t + 1)] = fmaf(v.y, inv, base + si);
            dst[IDX(t + 2)] = fmaf(v.z, inv, base + si2);
            dst[IDX(t + 3)] = fmaf(v.w, inv, base + si2 + si);
            tf += 256.0f;
        }
    }
    __syncthreads();

    const int p = tid >> 7;
    const int l = tid & 127;
    const int k0 = l * 32;
    const float* A = S->sm + (p * 2 + 0) * CSK;
    const float* B = S->sm + (p * 2 + 1) * CSK;

    int lo = (k0 > T_DIM) ? (k0 - T_DIM) : 0;
    int hi = (k0 < T_DIM) ? k0 : T_DIM;
    while (lo < hi) {
        int mid = (lo + hi) >> 1;
        if (A[IDX(mid)] <= B[IDX(k0 - 1 - mid)]) lo = mid + 1;
        else hi = mid;
    }
    int i = lo;
    int j = k0 - lo;

    float prevA = i ? A[IDX(i - 1)] : 0.0f;
    float prevB = j ? B[IDX(j - 1)] : 0.0f;
    float prev0 = fmaxf(prevA, prevB);
    float aq = (i < T_DIM) ? A[IDX(i)] : FLT_MAX;
    float bq = (j < T_DIM) ? B[IDX(j)] : FLT_MAX;
    float acc = 0.0f;

    if ((tid & 64) == 0) {
        // LEAN (ranks <= 2047): Abel form + EXACT per-chunk boundary correction:
        //   sum (q_k - q_{k-1}) fd_k^2 = [sum q_k (fd_k^2 - fd_{k+1}^2)]
        //                               - prev0*fd_first^2 + q_last*fd_final^2
        float fd0 = (float)(i - j);
        float fd2 = fd0 + fd0;              // 2*fd, updated in-loop
        acc = -prev0 * (fd0 * fd0);         // entry boundary term
        float lastq = prev0;
        #pragma unroll 8
        for (int s = 0; s < 32; s++) {
            bool takeA = (aq <= bq);
            float q = fminf(aq, bq);
            float sd = takeA ? -1.0f : 1.0f;
            float w = fmaf(sd, fd2, -1.0f);     // A: -(2fd+1)  B: (2fd-1)
            acc = fmaf(q, w, acc);
            fd2 = fmaf(-2.0f, sd, fd2);
            lastq = q;
            if (takeA) { i++; aq = A[IDX(i)]; }
            else       { j++; bq = B[IDX(j)]; }
        }
        float fdN = fd2 * 0.5f;
        acc = fmaf(lastq, fdN * fdN, acc);  // exit boundary term
    } else {
        // CLAMPED (ranks >= 2048): explicit prev-form with index clamps.
        float prev = prev0;
        #pragma unroll 8
        for (int s = 0; s < 32; s++) {
            bool takeA = (aq <= bq);
            float q = fminf(aq, bq);
            int ic = (i < 2047) ? i : 2047;
            int jc = (j < 2047) ? j : 2047;
            float diff = (float)(ic - jc);
            acc += (q - prev) * (diff * diff);
            prev = q;
            if (takeA) { i++; aq = (i < T_DIM) ? A[IDX(i)] : FLT_MAX; }
            else       { j++; bq = (j < T_DIM) ? B[IDX(j)] : FLT_MAX; }
        }
    }
    acc *= (1.0f / 2048.0f) * (1.0f / 2048.0f);

    for (int o = 16; o; o >>= 1) acc += __shfl_xor_sync(0xffffffffu, acc, o);
    if ((tid & 31) == 0) S->warr[tid >> 5] = acc;
    __syncthreads();
    if (tid == 0) {
        float s = 0.0f;
        #pragma unroll
        for (int i2 = 0; i2 < 8; i2++) s += S->warr[i2];
        atomicAdd(&out[bs >> 3], s);
    }
}

// ---------------- K1: cdf(bs0-15, min tracked) interleaved with min-only(bs16-31) ----------------
__global__ void __launch_bounds__(256) k1_kernel(const float* __restrict__ x,
                                                 const float* __restrict__ y,
                                                 float* __restrict__ out) {
    __shared__ SmemU S;
    const int tid = threadIdx.x;
    const int bid = blockIdx.x;
    if (bid == 0 && tid < 4) out[tid] = 0.0f;

    float mn;
    if (bid & 1) {
        // min-only: 32768 floats of the bs16-31 half, REVERSED so low-bs is L2-warm at end
        const int m = 511 - (bid >> 1);
        const float4* p = (const float4*)((m < 256 ? x : y)
                          + (size_t)16 * T_DIM * R_DIM + (size_t)(m & 255) * 32768);
        mn = FLT_MAX;
        #pragma unroll 8
        for (int k2 = 0; k2 < 32; k2++) {
            float4 v = p[k2 * 256 + tid];
            mn = fminf(mn, fminf(fminf(v.x, v.y), fminf(v.z, v.w)));
        }
    } else {
        const int c    = bid >> 1;            // 0..511
        const int a    = c >> 8;
        const int rem  = c & 255;
        const int bs   = rem >> 4;            // 0..15
        const int rem2 = rem & 15;
        const int r0   = (rem2 >> 1) * 32;
        const int tb   = (rem2 & 1) * 1024;
        mn = do_cdf(a ? y : x, a, bs, r0, tb, &S, tid & 31, tid >> 5, true);
    }

    for (int o = 16; o; o >>= 1) mn = fminf(mn, __shfl_xor_sync(0xffffffffu, mn, o));
    if ((tid & 31) == 0) S.wmin[tid >> 5] = mn;
    __syncthreads();
    if (tid == 0) {
        float m = S.wmin[0];
        #pragma unroll
        for (int i = 1; i < 8; i++) m = fminf(m, S.wmin[i]);
        g_blockmin[bid] = m;
    }
}

// ---------------- K2: cdf(bs16-31, reversed) 1-in-5 interleaved with w2(bs0-15, reversed) ----------------
__global__ void __launch_bounds__(256) k2_kernel(const float* __restrict__ x,
                                                 const float* __restrict__ y,
                                                 float* __restrict__ out) {
    __shared__ SmemU S;
    const int tid = threadIdx.x;
    const int bid = blockIdx.x;

    if (bid % 5 == 0) {
        const int c    = 511 - bid / 5;       // reversed: bs31 written first
        const int a    = c >> 8;
        const int rem  = c & 255;
        const int bs   = 16 + (rem >> 4);     // 16..31
        const int rem2 = rem & 15;
        const int r0   = (rem2 >> 1) * 32;
        const int tb   = (rem2 & 1) * 1024;
        do_cdf(a ? y : x, a, bs, r0, tb, &S, tid & 31, tid >> 5, false);
    } else {
        const int w  = bid - bid / 5 - 1;     // 0..2047
        const int bs = 15 - (w >> 7);         // reversed: newest-written g_cdf first
        const int r0 = (w & 127) * 2;
        do_w2(bs, r0, out, &S, tid);
    }
}

// ---------------- K3: w2(bs16-31) ----------------
__global__ void __launch_bounds__(256) k3_kernel(float* __restrict__ out) {
    __shared__ SmemU S;
    const int w  = blockIdx.x;
    const int bs = 31 - (w >> 7);             // reversed: newest-written g_cdf first
    const int r0 = (w & 127) * 2;
    do_w2(bs, r0, out, &S, threadIdx.x);
}

extern "C" void kernel_launch(void* const* d_in, const int* in_sizes, int n_in,
                              void* d_out, int out_size) {
    const float* x = (const float*)d_in[0];
    const float* y = (const float*)d_in[1];
    float* out = (float*)d_out;

    k1_kernel<<<1024, 256>>>(x, y, out);
    k2_kernel<<<2560, 256>>>(x, y, out);
    k3_kernel<<<2048, 256>>>(out);
}